// round 14
// baseline (speedup 1.0000x reference)
#include <cuda_runtime.h>

// ConvexSampler: out = concat(flatten(z), flatten(convex_rows), labels_f32, data_type_f32)
//   z:         (B, D) float32  d_in[0]
//   label_ids: (B,)   int32    d_in[1]
//   data_type: (B,)   float32  d_in[2]
//   pair_idx:  (NC,2) int32    d_in[3]
//   s:         (NC,)  float32  d_in[4]
//   oos_label_id: scalar int   d_in[5] (if present)
//
// Grid fixed at measured optimum: 4736 blocks (4 full waves @ 256 thr, 8/SM).
// Copy blocks process contiguous 16KB chunks (1024 float4): thread t moves
// chunk+t, +256, +512, +768 -> coalesced, MLP=4, and each CTA's traffic is
// spatially local (one DRAM region per iteration instead of 4 spread 19MB
// apart). Extras blocks handle convex rows + tails concurrently.

#define EX_BLOCKS 16
#define TOTAL_BLOCKS 4736
#define CHUNK4 1024LL   // float4 per chunk = 4 * 256 threads

__global__ void __launch_bounds__(256, 8)
convex_sampler_fused(const float* __restrict__ z,
                     const int* __restrict__ label_ids,
                     const float* __restrict__ data_type,
                     const int* __restrict__ pair_idx,
                     const float* __restrict__ s,
                     const int* __restrict__ oos_ptr,
                     float* __restrict__ out,
                     int B, int D, int NC)
{
    const long long D4  = D / 4;
    const long long BD4 = (long long)B * D4;      // float4 count of z copy

    const float4* __restrict__ z4  = (const float4*)z;
    float4* __restrict__ out4 = (float4*)out;

    if (blockIdx.x >= EX_BLOCKS) {
        // ---- Region A: contiguous-chunk copy, MLP=4, coalesced ----
        const int nCopy = gridDim.x - EX_BLOCKS;
        const long long nChunks = BD4 / CHUNK4;           // full chunks
        const int t = threadIdx.x;

        for (long long c = blockIdx.x - EX_BLOCKS; c < nChunks; c += nCopy) {
            const long long base = c * CHUNK4 + t;
            float4 a = z4[base];
            float4 b = z4[base + 256];
            float4 cc = z4[base + 512];
            float4 d = z4[base + 768];
            out4[base]       = a;
            out4[base + 256] = b;
            out4[base + 512] = cc;
            out4[base + 768] = d;
        }
        // tail (BD4 not multiple of CHUNK4)
        const long long tailStart = nChunks * CHUNK4;
        for (long long i = tailStart + (long long)(blockIdx.x - EX_BLOCKS) * blockDim.x + t;
             i < BD4; i += (long long)nCopy * blockDim.x)
            out4[i] = z4[i];
    } else {
        // ---- Extras: convex rows + labels + data_type (tiny; concurrent) ----
        const long long CV4 = (long long)NC * D4;
        const long long NT  = (long long)B + NC;
        const long long scalarBase = (BD4 + CV4) * 4;
        const long long total = CV4 + 2 * NT;

        float oos = 150.0f;
        if (oos_ptr) oos = (float)(*oos_ptr);

        const long long stride = (long long)EX_BLOCKS * blockDim.x;
        for (long long i = (long long)blockIdx.x * blockDim.x + threadIdx.x;
             i < total; i += stride) {
            if (i < CV4) {
                int row  = (int)(i / D4);
                int col4 = (int)(i - (long long)row * D4);
                long long a = (long long)pair_idx[2 * row];
                long long b = (long long)pair_idx[2 * row + 1];
                float sv = s[row];
                float tv = 1.0f - sv;
                float4 za = z4[a * D4 + col4];
                float4 zb = z4[b * D4 + col4];
                float4 r;
                r.x = sv * za.x + tv * zb.x;
                r.y = sv * za.y + tv * zb.y;
                r.z = sv * za.z + tv * zb.z;
                r.w = sv * za.w + tv * zb.w;
                out4[BD4 + i] = r;
            } else if (i < CV4 + NT) {
                long long k = i - CV4;
                float v = (k < B) ? (float)label_ids[k] : oos;
                out[scalarBase + k] = v;
            } else {
                long long k = i - CV4 - NT;
                float v = (k < B) ? data_type[k] : 1.0f;
                out[scalarBase + NT + k] = v;
            }
        }
    }
}

extern "C" void kernel_launch(void* const* d_in, const int* in_sizes, int n_in,
                              void* d_out, int out_size)
{
    const float* z         = (const float*)d_in[0];
    const int*   label_ids = (const int*)d_in[1];
    const float* data_type = (const float*)d_in[2];
    const int*   pair_idx  = (const int*)d_in[3];
    const float* s         = (const float*)d_in[4];
    const int*   oos_ptr   = (n_in >= 6) ? (const int*)d_in[5] : nullptr;

    int B  = in_sizes[1];
    int D  = in_sizes[0] / B;
    int NC = in_sizes[4];

    (void)out_size;

    const int threads = 256;
    convex_sampler_fused<<<TOTAL_BLOCKS, threads>>>(z, label_ids, data_type, pair_idx, s,
                                                    oos_ptr, (float*)d_out, B, D, NC);
}